// round 8
// baseline (speedup 1.0000x reference)
#include <cuda_runtime.h>
#include <stdint.h>

#define N      1024
#define STEPS  32
#define TTOT   1900.0f
#define T0     1880.0f
#define NT     256            // threads per block
#define NB     512            // blocks, 2 rows each; co-resident: 4/SM x 148 = 592 >= 512
#define RPB    2
#define SW     1028           // shared row stride (pad 4 to break conflicts)

// fp64 compile-time fold, then cast to fp32
#define C_FD ((float)(1e-16 * (910.0 * 9.81) * (910.0 * 9.81) * (910.0 * 9.81)))

// Scratch (device globals — no allocations allowed)
__device__ float        g_Hbuf[N * N];
__device__ unsigned int g_maxD[STEPS];
__device__ unsigned int g_count;            // barrier arrival counter (monotonic)
__device__ volatile unsigned int g_release; // barrier release generation

// ---------------------------------------------------------------------------
__global__ void init_kernel(const float* __restrict__ Hinit, float* __restrict__ H0) {
    int idx = blockIdx.x * blockDim.x + threadIdx.x;
    int stride = gridDim.x * blockDim.x;
    const float4* src = (const float4*)Hinit;
    float4* dst = (float4*)H0;
    for (int i = idx; i < N * N / 4; i += stride) dst[i] = src[i];
    if (idx < STEPS) g_maxD[idx] = 0u;
    if (idx == STEPS) { g_count = 0u; g_release = 0u; }
}

// ---------------------------------------------------------------------------
// Grid barrier: one atomicAdd/block; LAST arriver publishes release.
// Generation-counted, reset by init_kernel each replay. Grid is co-resident.
__device__ __forceinline__ void grid_sync(unsigned int gen) {
    __syncthreads();
    if (threadIdx.x == 0) {
        __threadfence();
        unsigned int prev = atomicAdd(&g_count, 1u);
        if (prev == gen * NB - 1u) {
            __threadfence();
            g_release = gen;
        } else {
            while (g_release < gen) __nanosleep(40);
        }
        __threadfence();
    }
    __syncthreads();
}

__device__ __forceinline__ float4 ld4(const float* p) {
    return *reinterpret_cast<const float4*>(p);
}

// ---------------------------------------------------------------------------
__global__ void __launch_bounds__(NT, 4)
glacier_persist(float* __restrict__ buf0,          // = d_out
                float* __restrict__ buf1,          // = g_Hbuf
                const float* __restrict__ Zt,
                const float* __restrict__ Zela)
{
    // shared: [guard 16][Zs 4 rows][H 4 rows][D 3 rows]  (flat, ~44.3 KB)
    __shared__ float smem[16 + (4 + 4 + 3) * SW];
    __shared__ unsigned int s_max;
    float* s_zs = smem + 16;           // rows r0-1 .. r0+2
    float* s_h  = s_zs + 4 * SW;       // rows r0-1 .. r0+2
    float* s_d  = s_h + 4 * SW;        // D rows r0-1 .. r0+1

    const int tid = threadIdx.x;
    const int r0  = blockIdx.x * RPB;
    const int c0  = 4 * tid;

    float t = T0;
    unsigned int gen = 0;

    for (int s = 0; s < STEPS; s++) {
        // -------- early exit: dt == 0 for all remaining steps (identity) ------
        if (!(t < TTOT)) {
            if (s & 1) {
                #pragma unroll
                for (int rr = 0; rr < RPB; rr++) {
                    int r = r0 + rr;
                    *(float4*)&buf0[r * N + c0] = ld4(&buf1[r * N + c0]);
                }
            }
            return;
        }

        const float* Hc = (s & 1) ? buf1 : buf0;
        float*       Hn = (s & 1) ? buf0 : buf1;

        if (tid == 0) s_max = 0u;

        // ---------- fill shared: H and Zs for rows r0-1 .. r0+2 ----------
        #pragma unroll
        for (int rr = 0; rr < 4; rr++) {
            int r = r0 - 1 + rr;
            float4 hv = make_float4(0.f, 0.f, 0.f, 0.f);
            float4 zv = hv;
            if (r >= 0 && r < N) {
                hv = ld4(&Hc[r * N + c0]);
                zv = ld4(&Zt[r * N + c0]);
            }
            *(float4*)&s_h[rr * SW + c0] = hv;
            *(float4*)&s_zs[rr * SW + c0] =
                make_float4(zv.x + hv.x, zv.y + hv.y, zv.z + hv.z, zv.w + hv.w);
        }
        __syncthreads();

        // ---------- D rows r0-1 .. r0+1 into shared; max over owned rows ------
        unsigned int lmax = 0u;
        #pragma unroll
        for (int rr = 0; rr < 3; rr++) {
            int r = r0 - 1 + rr;
            if (r >= 0 && r <= N - 2) {
                float dv[4];
                #pragma unroll
                for (int j = 0; j < 4; j++) {
                    int c = c0 + j;
                    float h00 = s_h[rr * SW + c],       h01 = s_h[rr * SW + c + 1];
                    float h10 = s_h[(rr + 1) * SW + c], h11 = s_h[(rr + 1) * SW + c + 1];
                    float z00 = s_zs[rr * SW + c],       z01 = s_zs[rr * SW + c + 1];
                    float z10 = s_zs[(rr + 1) * SW + c], z11 = s_zs[(rr + 1) * SW + c + 1];
                    float havg = 0.25f * (h00 + h11 + h01 + h10);
                    float sx = 0.5f * ((z01 - z00) / 100.0f + (z11 - z10) / 100.0f);
                    float sy = 0.5f * ((z10 - z00) / 100.0f + (z11 - z01) / 100.0f);
                    float sn2 = sx * sx + sy * sy + 1e-20f;
                    float h2 = havg * havg;
                    float h5 = h2 * h2 * havg;
                    dv[j] = C_FD * h5 * sn2 + 1e-20f;
                }
                if (c0 + 3 == N - 1) dv[3] = 0.0f;   // col 1023 is not a D cell
                *(float4*)&s_d[rr * SW + c0] = make_float4(dv[0], dv[1], dv[2], dv[3]);
                if (rr >= 1) {                        // owned rows only (halo rr==0)
                    #pragma unroll
                    for (int j = 0; j < 4; j++) {
                        unsigned int db = __float_as_uint(dv[j]);
                        if (db > lmax) lmax = db;
                    }
                }
            }
        }
        unsigned int wmax = __reduce_max_sync(0xffffffffu, lmax);
        if ((tid & 31) == 0) atomicMax(&s_max, wmax);
        __syncthreads();                              // s_d complete, s_max done
        if (tid == 0) atomicMax(&g_maxD[s], s_max);

        // ---------- H update (shared-only stencil reads) ----------
        auto do_update = [&](float dt) {
            #pragma unroll
            for (int rr = 0; rr < RPB; rr++) {
                int r = r0 + rr;
                int srow = rr + 1;                     // shared row index of global r
                if (r == 0 || r == N - 1) {
                    float4 v = ld4(&s_h[srow * SW + c0]);
                    *(float4*)&Hn[r * N + c0] =
                        make_float4(fmaxf(v.x, 0.f), fmaxf(v.y, 0.f),
                                    fmaxf(v.z, 0.f), fmaxf(v.w, 0.f));
                } else {
                    float4 el = ld4(&Zela[r * N + c0]);
                    float elv[4] = { el.x, el.y, el.z, el.w };
                    float out[4];
                    #pragma unroll
                    for (int j = 0; j < 4; j++) {
                        int c = c0 + j;
                        float h = s_h[srow * SW + c];
                        if (c == 0 || c == N - 1) {
                            out[j] = fmaxf(h, 0.0f);
                        } else {
                            float zc = s_zs[srow * SW + c];
                            float zl = s_zs[srow * SW + c - 1];
                            float zr = s_zs[srow * SW + c + 1];
                            float zu = s_zs[(srow - 1) * SW + c];
                            float zd = s_zs[(srow + 1) * SW + c];
                            float Dul = s_d[rr * SW + c - 1];
                            float Dur = s_d[rr * SW + c];
                            float Dll = s_d[(rr + 1) * SW + c - 1];
                            float Dlr = s_d[(rr + 1) * SW + c];

                            float qxL = -(0.5f * (Dul + Dll)) * (zc - zl) / 100.0f;
                            float qxR = -(0.5f * (Dur + Dlr)) * (zr - zc) / 100.0f;
                            float qyU = -(0.5f * (Dul + Dur)) * (zc - zu) / 100.0f;
                            float qyD = -(0.5f * (Dll + Dlr)) * (zd - zc) / 100.0f;

                            float dHdt = -((qxR - qxL) / 100.0f + (qyD - qyU) / 100.0f);
                            float b = fminf(1e-3f * (zc - elv[j]), 0.3f);
                            out[j] = fmaxf(h + dt * (dHdt + b), 0.0f);
                        }
                    }
                    *(float4*)&Hn[r * N + c0] = make_float4(out[0], out[1], out[2], out[3]);
                }
            }
        };

        // Speculative update with dt = 1 (exact when dt_true == 1: x*1.0f == x)
        do_update(1.0f);

        grid_sync(++gen);

        // Verify speculation against the true global max(D)
        unsigned int mbits = *(volatile unsigned int*)&g_maxD[s];
        float maxD = __uint_as_float(mbits);
        float dt = fminf(10000.0f / (2.7f * maxD), 1.0f);
        if (dt != 1.0f) {
            // slow path (never taken for this physics): Hc intact, s_zs/s_h/s_d valid
            do_update(dt);
            grid_sync(++gen);
        }
        t += dt;
    }
    // 32 steps without exit: STEPS even -> result in buf0 == d_out
}

// ---------------------------------------------------------------------------
extern "C" void kernel_launch(void* const* d_in, const int* in_sizes, int n_in,
                              void* d_out, int out_size) {
    const float* Zela  = (const float*)d_in[0];
    const float* Ztopo = (const float*)d_in[1];
    const float* Hinit = (const float*)d_in[2];
    float* out = (float*)d_out;

    float* hbuf = nullptr;
    cudaGetSymbolAddress((void**)&hbuf, g_Hbuf);

    init_kernel<<<NB, NT>>>(Hinit, out);
    glacier_persist<<<NB, NT>>>(out, hbuf, Ztopo, Zela);
}

// round 16
// speedup vs baseline: 1.4699x; 1.4699x over previous
#include <cuda_runtime.h>
#include <stdint.h>

#define N      1024
#define STEPS  32
#define TTOT   1900.0f
#define T0     1880.0f
#define NT     256            // threads per block
#define NB     512            // blocks (2 rows each) — co-resident: 4/SM x 148 = 592 >= 512
#define RPB    2              // rows per block

// fp64 compile-time fold, then cast to fp32
#define C_FD ((float)(1e-16 * (910.0 * 9.81) * (910.0 * 9.81) * (910.0 * 9.81)))

// Scratch (device globals — no allocations allowed)
__device__ float        g_Hbuf[N * N];      // ping-pong partner of d_out
__device__ float        g_D[N * N];         // D, padded to stride N (rows 0..1022 used)
__device__ unsigned int g_maxD[STEPS];
__device__ unsigned int g_count;            // barrier arrival counter (monotonic)
__device__ volatile unsigned int g_release; // barrier release generation

// ---------------------------------------------------------------------------
__global__ void init_kernel(const float* __restrict__ Hinit, float* __restrict__ H0) {
    int idx = blockIdx.x * blockDim.x + threadIdx.x;
    int stride = gridDim.x * blockDim.x;
    const float4* src = (const float4*)Hinit;
    float4* dst = (float4*)H0;
    for (int i = idx; i < N * N / 4; i += stride) dst[i] = src[i];
    if (idx < STEPS) g_maxD[idx] = 0u;
    if (idx == STEPS) { g_count = 0u; g_release = 0u; }
}

// ---------------------------------------------------------------------------
// Grid barrier: one atomicAdd per block (parallel-friendly single-address RED),
// LAST arriver publishes release; spinners nanosleep-poll one line.
// Generation-counted, reset by init_kernel each replay. Grid is co-resident.
__device__ __forceinline__ void grid_sync(unsigned int gen) {
    __syncthreads();
    if (threadIdx.x == 0) {
        __threadfence();
        unsigned int prev = atomicAdd(&g_count, 1u);
        if (prev == gen * NB - 1u) {
            __threadfence();
            g_release = gen;               // last arriver releases
        } else {
            while (g_release < gen) __nanosleep(100);
        }
        __threadfence();
    }
    __syncthreads();
}

__device__ __forceinline__ float4 ld4(const float* p) {
    return *reinterpret_cast<const float4*>(p);
}

// ---------------------------------------------------------------------------
__global__ void __launch_bounds__(NT, 4)
glacier_persist(float* __restrict__ buf0,          // = d_out
                float* __restrict__ buf1,          // = g_Hbuf
                const float* __restrict__ Zt,      // Z_topo
                const float* __restrict__ Zela)
{
    const int tid = threadIdx.x;
    const int r0  = blockIdx.x * RPB;
    const int c0  = 4 * tid;

    __shared__ unsigned int s_max;
    float t = T0;
    unsigned int gen = 0;

    for (int s = 0; s < STEPS; s++) {
        // -------- early exit: dt == 0 for all remaining steps (identity) ------
        if (!(t < TTOT)) {
            if (s & 1) {  // result lives in buf1 -> move own rows to buf0
                #pragma unroll
                for (int rr = 0; rr < RPB; rr++) {
                    int r = r0 + rr;
                    *(float4*)&buf0[r * N + c0] = ld4(&buf1[r * N + c0]);
                }
            }
            return;
        }

        const float* Hc = (s & 1) ? buf1 : buf0;
        float*       Hn = (s & 1) ? buf0 : buf1;

        // ---------------- Phase A: diffusivity + max ----------------
        if (tid == 0) s_max = 0u;
        __syncthreads();

        unsigned int lmax = 0u;
        #pragma unroll
        for (int rr = 0; rr < RPB; rr++) {
            int r = r0 + rr;
            if (r <= N - 2) {
                float4 hA = ld4(&Hc[r * N + c0]);
                float4 hB = ld4(&Hc[(r + 1) * N + c0]);
                float4 zA = ld4(&Zt[r * N + c0]);
                float4 zB = ld4(&Zt[(r + 1) * N + c0]);
                float hA4 = 0.f, hB4 = 0.f, zA4 = 0.f, zB4 = 0.f;
                if (tid < NT - 1) {
                    hA4 = Hc[r * N + c0 + 4];
                    hB4 = Hc[(r + 1) * N + c0 + 4];
                    zA4 = Zt[r * N + c0 + 4];
                    zB4 = Zt[(r + 1) * N + c0 + 4];
                }
                float ha[5] = {hA.x, hA.y, hA.z, hA.w, hA4};
                float hb[5] = {hB.x, hB.y, hB.z, hB.w, hB4};
                float za[5] = {zA.x, zA.y, zA.z, zA.w, zA4};
                float zb[5] = {zB.x, zB.y, zB.z, zB.w, zB4};
                float dv[4];
                #pragma unroll
                for (int j = 0; j < 4; j++) {
                    float h00 = ha[j], h01 = ha[j + 1];
                    float h10 = hb[j], h11 = hb[j + 1];
                    float z00 = za[j] + h00, z01 = za[j + 1] + h01;
                    float z10 = zb[j] + h10, z11 = zb[j + 1] + h11;
                    float havg = 0.25f * (h00 + h11 + h01 + h10);
                    float sx = 0.5f * ((z01 - z00) / 100.0f + (z11 - z10) / 100.0f);
                    float sy = 0.5f * ((z10 - z00) / 100.0f + (z11 - z01) / 100.0f);
                    float sn2 = sx * sx + sy * sy + 1e-20f;
                    float h2 = havg * havg;
                    float h5 = h2 * h2 * havg;
                    dv[j] = C_FD * h5 * sn2 + 1e-20f;
                }
                if (tid == NT - 1) dv[3] = 0.0f;   // col 1023: padding, not a D cell
                #pragma unroll
                for (int j = 0; j < 4; j++) {
                    unsigned int db = __float_as_uint(dv[j]);  // d >= 0 -> uint-ordered
                    if (db > lmax) lmax = db;
                }
                *(float4*)&g_D[r * N + c0] = make_float4(dv[0], dv[1], dv[2], dv[3]);
            }
        }
        unsigned int wmax = __reduce_max_sync(0xffffffffu, lmax);
        if ((tid & 31) == 0) atomicMax(&s_max, wmax);
        __syncthreads();
        if (tid == 0) atomicMax(&g_maxD[s], s_max);

        grid_sync(++gen);

        // ---------------- Phase B: H update ----------------
        float maxD = __uint_as_float(g_maxD[s]);
        float dt = fminf(10000.0f / (2.7f * maxD), 1.0f);   // t < TTOT guaranteed here

        #pragma unroll
        for (int rr = 0; rr < RPB; rr++) {
            int r = r0 + rr;
            if (r == 0 || r == N - 1) {
                float4 v = ld4(&Hc[r * N + c0]);
                *(float4*)&Hn[r * N + c0] =
                    make_float4(fmaxf(v.x, 0.f), fmaxf(v.y, 0.f),
                                fmaxf(v.z, 0.f), fmaxf(v.w, 0.f));
            } else {
                float4 hM = ld4(&Hc[(r - 1) * N + c0]);
                float4 hC = ld4(&Hc[r * N + c0]);
                float4 hP = ld4(&Hc[(r + 1) * N + c0]);
                float4 zM = ld4(&Zt[(r - 1) * N + c0]);
                float4 zC = ld4(&Zt[r * N + c0]);
                float4 zP = ld4(&Zt[(r + 1) * N + c0]);
                float4 dM = ld4(&g_D[(r - 1) * N + c0]);
                float4 dC = ld4(&g_D[r * N + c0]);
                float4 el = ld4(&Zela[r * N + c0]);

                float hCl = 0.f, zCl = 0.f, dMl = 0.f, dCl = 0.f;
                float hCr = 0.f, zCr = 0.f;
                if (tid > 0) {
                    hCl = Hc[r * N + c0 - 1];
                    zCl = Zt[r * N + c0 - 1];
                    dMl = g_D[(r - 1) * N + c0 - 1];
                    dCl = g_D[r * N + c0 - 1];
                }
                if (tid < NT - 1) {
                    hCr = Hc[r * N + c0 + 4];
                    zCr = Zt[r * N + c0 + 4];
                }
                // Zs at cols c0-1 .. c0+4
                float zs[6] = { zCl + hCl, zC.x + hC.x, zC.y + hC.y,
                                zC.z + hC.z, zC.w + hC.w, zCr + hCr };
                float hcv[4] = { hC.x, hC.y, hC.z, hC.w };
                float zuv[4] = { zM.x + hM.x, zM.y + hM.y, zM.z + hM.z, zM.w + hM.w };
                float zdv[4] = { zP.x + hP.x, zP.y + hP.y, zP.z + hP.z, zP.w + hP.w };
                float dm[5]  = { dMl, dM.x, dM.y, dM.z, dM.w };   // D[r-1], cols c0-1..c0+3
                float dcv[5] = { dCl, dC.x, dC.y, dC.z, dC.w };   // D[r],   cols c0-1..c0+3
                float elv[4] = { el.x, el.y, el.z, el.w };
                float out[4];
                #pragma unroll
                for (int j = 0; j < 4; j++) {
                    int c = c0 + j;
                    float h = hcv[j];
                    if (c == 0 || c == N - 1) {
                        out[j] = fmaxf(h, 0.0f);
                    } else {
                        float zc = zs[j + 1], zl = zs[j], zr = zs[j + 2];
                        float zu = zuv[j], zd = zdv[j];
                        float Dul = dm[j], Dur = dm[j + 1];
                        float Dll = dcv[j], Dlr = dcv[j + 1];

                        float qxL = -(0.5f * (Dul + Dll)) * (zc - zl) / 100.0f;
                        float qxR = -(0.5f * (Dur + Dlr)) * (zr - zc) / 100.0f;
                        float qyU = -(0.5f * (Dul + Dur)) * (zc - zu) / 100.0f;
                        float qyD = -(0.5f * (Dll + Dlr)) * (zd - zc) / 100.0f;

                        float dHdt = -((qxR - qxL) / 100.0f + (qyD - qyU) / 100.0f);
                        float b = fminf(1e-3f * (zc - elv[j]), 0.3f);
                        out[j] = fmaxf(h + dt * (dHdt + b), 0.0f);
                    }
                }
                *(float4*)&Hn[r * N + c0] = make_float4(out[0], out[1], out[2], out[3]);
            }
        }
        t += dt;

        grid_sync(++gen);
    }
    // all 32 steps done: STEPS even -> result in buf0 == d_out
}

// ---------------------------------------------------------------------------
extern "C" void kernel_launch(void* const* d_in, const int* in_sizes, int n_in,
                              void* d_out, int out_size) {
    const float* Zela  = (const float*)d_in[0];
    const float* Ztopo = (const float*)d_in[1];
    const float* Hinit = (const float*)d_in[2];
    float* out = (float*)d_out;

    float* hbuf = nullptr;
    cudaGetSymbolAddress((void**)&hbuf, g_Hbuf);

    init_kernel<<<NB, NT>>>(Hinit, out);
    glacier_persist<<<NB, NT>>>(out, hbuf, Ztopo, Zela);
}